// round 3
// baseline (speedup 1.0000x reference)
#include <cuda_runtime.h>
#include <math.h>

// Problem shape (fixed by the reference)
#define BB    2
#define SS    2048
#define DD    1024
#define HH    16
#define DKK   64
#define DFFN  4096
#define MROWS (BB*SS)   // 4096 token rows

// ---------------------------------------------------------------------------
// Scratch (device globals: allocation inside kernel_launch is forbidden)
// ---------------------------------------------------------------------------
__device__ float g_h  [MROWS*DD];    // ln1(x)
__device__ float g_q  [MROWS*DD];
__device__ float g_k  [MROWS*DD];
__device__ float g_v  [MROWS*DD];
__device__ float g_ctx[MROWS*DD];    // attention context
__device__ float g_x2 [MROWS*DD];    // x + attn out-proj
__device__ float g_h2 [MROWS*DD];    // ln2(x2)
__device__ float g_ff [MROWS*DFFN];  // relu(h2@W1+b1)

// ---------------------------------------------------------------------------
// LayerNorm: alpha * (x - mean) / (std_ddof1 + eps) + beta   (scalars a, g)
// ---------------------------------------------------------------------------
__global__ __launch_bounds__(256) void ln_kernel(
    const float* __restrict__ x, float* __restrict__ out,
    const float* __restrict__ pa, const float* __restrict__ pg)
{
    int row = blockIdx.x;
    int t   = threadIdx.x;
    const float4* xr = (const float4*)(x + (size_t)row * DD);
    float4 v = xr[t];
    float s  = v.x + v.y + v.z + v.w;
    float sq = v.x*v.x + v.y*v.y + v.z*v.z + v.w*v.w;
#pragma unroll
    for (int o = 16; o > 0; o >>= 1) {
        s  += __shfl_xor_sync(0xffffffffu, s,  o);
        sq += __shfl_xor_sync(0xffffffffu, sq, o);
    }
    __shared__ float rs[8], rq[8];
    __shared__ float s_mean, s_inv;
    int w = t >> 5, lane = t & 31;
    if (lane == 0) { rs[w] = s; rq[w] = sq; }
    __syncthreads();
    if (t == 0) {
        float ts = 0.f, tq = 0.f;
#pragma unroll
        for (int i = 0; i < 8; i++) { ts += rs[i]; tq += rq[i]; }
        float mean = ts / (float)DD;
        float var  = (tq - (float)DD * mean * mean) / (float)(DD - 1);
        float stdv = sqrtf(fmaxf(var, 0.f));
        s_mean = mean;
        s_inv  = 1.f / (stdv + 1e-6f);
    }
    __syncthreads();
    float a = *pa, g = *pg;
    float mean = s_mean, inv = s_inv;
    float4 o;
    o.x = a * (v.x - mean) * inv + g;
    o.y = a * (v.y - mean) * inv + g;
    o.z = a * (v.z - mean) * inv + g;
    o.w = a * (v.w - mean) * inv + g;
    ((float4*)(out + (size_t)row * DD))[t] = o;
}

// ---------------------------------------------------------------------------
// TF32 tensor-core GEMM: C[M,N] = A[M,K] @ W[K,N] + bias (+relu) (+residual)
// Block 128x128xBK16, 256 threads = 8 warps (2m x 4n), warp tile 64x32.
// ---------------------------------------------------------------------------
__device__ __forceinline__ unsigned f2tf32(float x) {
    unsigned u;
    asm("cvt.rna.tf32.f32 %0, %1;" : "=r"(u) : "f"(x));
    return u;
}

template<bool RELU, bool RES>
__global__ __launch_bounds__(256) void tf32_gemm(
    const float* __restrict__ A, const float* __restrict__ W,
    const float* __restrict__ bias, const float* __restrict__ res,
    float* __restrict__ C, int M, int N, int K)
{
    const int BK = 16;
    __shared__ float As[128][20];
    __shared__ float Bs[16][136];

    int bn = blockIdx.x * 128;
    int bm = blockIdx.y * 128;
    int tid  = threadIdx.x;
    int lane = tid & 31;
    int warp = tid >> 5;
    int wm = warp & 1;
    int wn = warp >> 1;
    int g   = lane >> 2;
    int tig = lane & 3;

    float acc[4][4][4];
#pragma unroll
    for (int i = 0; i < 4; i++)
#pragma unroll
        for (int j = 0; j < 4; j++)
#pragma unroll
            for (int c = 0; c < 4; c++) acc[i][j][c] = 0.f;

    int aRow = tid >> 2;
    int aCol = (tid & 3) * 4;
    int bRow = tid >> 5;
    int bCol = (tid & 31) * 4;
    const float* Ap = A + (size_t)(bm + aRow) * K + aCol;
    const float* Bp = W + (size_t)bRow * N + bn + bCol;

    for (int k0 = 0; k0 < K; k0 += BK) {
        float4 av0 = *(const float4*)Ap;
        float4 av1 = *(const float4*)(Ap + (size_t)64 * K);
        float4 bv0 = *(const float4*)Bp;
        float4 bv1 = *(const float4*)(Bp + (size_t)8 * N);

        As[aRow     ][aCol + 0] = __uint_as_float(f2tf32(av0.x));
        As[aRow     ][aCol + 1] = __uint_as_float(f2tf32(av0.y));
        As[aRow     ][aCol + 2] = __uint_as_float(f2tf32(av0.z));
        As[aRow     ][aCol + 3] = __uint_as_float(f2tf32(av0.w));
        As[aRow + 64][aCol + 0] = __uint_as_float(f2tf32(av1.x));
        As[aRow + 64][aCol + 1] = __uint_as_float(f2tf32(av1.y));
        As[aRow + 64][aCol + 2] = __uint_as_float(f2tf32(av1.z));
        As[aRow + 64][aCol + 3] = __uint_as_float(f2tf32(av1.w));

        float4 bc0, bc1;
        bc0.x = __uint_as_float(f2tf32(bv0.x));
        bc0.y = __uint_as_float(f2tf32(bv0.y));
        bc0.z = __uint_as_float(f2tf32(bv0.z));
        bc0.w = __uint_as_float(f2tf32(bv0.w));
        bc1.x = __uint_as_float(f2tf32(bv1.x));
        bc1.y = __uint_as_float(f2tf32(bv1.y));
        bc1.z = __uint_as_float(f2tf32(bv1.z));
        bc1.w = __uint_as_float(f2tf32(bv1.w));
        *(float4*)&Bs[bRow    ][bCol] = bc0;
        *(float4*)&Bs[bRow + 8][bCol] = bc1;

        __syncthreads();

#pragma unroll
        for (int ks = 0; ks < 2; ks++) {
            int kk = ks * 8;
            unsigned af[4][4], bf[4][2];
#pragma unroll
            for (int mt = 0; mt < 4; mt++) {
                int m0 = wm * 64 + mt * 16;
                af[mt][0] = __float_as_uint(As[m0 + g    ][kk + tig    ]);
                af[mt][1] = __float_as_uint(As[m0 + g + 8][kk + tig    ]);
                af[mt][2] = __float_as_uint(As[m0 + g    ][kk + tig + 4]);
                af[mt][3] = __float_as_uint(As[m0 + g + 8][kk + tig + 4]);
            }
#pragma unroll
            for (int nt = 0; nt < 4; nt++) {
                int n0 = wn * 32 + nt * 8;
                bf[nt][0] = __float_as_uint(Bs[kk + tig    ][n0 + g]);
                bf[nt][1] = __float_as_uint(Bs[kk + tig + 4][n0 + g]);
            }
#pragma unroll
            for (int mt = 0; mt < 4; mt++)
#pragma unroll
                for (int nt = 0; nt < 4; nt++) {
                    asm volatile(
                        "mma.sync.aligned.m16n8k8.row.col.f32.tf32.tf32.f32 "
                        "{%0,%1,%2,%3}, {%4,%5,%6,%7}, {%8,%9}, {%0,%1,%2,%3};"
                        : "+f"(acc[mt][nt][0]), "+f"(acc[mt][nt][1]),
                          "+f"(acc[mt][nt][2]), "+f"(acc[mt][nt][3])
                        : "r"(af[mt][0]), "r"(af[mt][1]),
                          "r"(af[mt][2]), "r"(af[mt][3]),
                          "r"(bf[nt][0]), "r"(bf[nt][1]));
                }
        }
        __syncthreads();
        Ap += BK;
        Bp += (size_t)BK * N;
    }

#pragma unroll
    for (int mt = 0; mt < 4; mt++) {
#pragma unroll
        for (int nt = 0; nt < 4; nt++) {
            int m0 = bm + wm * 64 + mt * 16 + g;
            int n0 = bn + wn * 32 + nt * 8 + tig * 2;
            float bx = bias[n0], by = bias[n0 + 1];
#pragma unroll
            for (int half = 0; half < 2; half++) {
                int m = m0 + half * 8;
                float rx = acc[mt][nt][half * 2 + 0] + bx;
                float ry = acc[mt][nt][half * 2 + 1] + by;
                if (RELU) { rx = fmaxf(rx, 0.f); ry = fmaxf(ry, 0.f); }
                size_t off = (size_t)m * N + n0;
                if (RES) {
                    float2 rr = *(const float2*)(res + off);
                    rx += rr.x; ry += rr.y;
                }
                float2 o2; o2.x = rx; o2.y = ry;
                *(float2*)(C + off) = o2;
            }
        }
    }
}

// ---------------------------------------------------------------------------
// Fused flash attention with tf32 mma (mask is a no-op in the reference).
// Block: 256 threads = 8 warps. Tile: 128 q-rows x 64 kv. Each warp owns a
// 16-row m-tile across all 64 kv cols / 64 d cols, so softmax row stats
// reduce within a quad (shfl_xor 1,2).
// smem floats: Qs[128][68] | Ps[128][68] | Ks[64][68] | Vs[64][72]
// Strides chosen so all mma fragment loads are 32-bank conflict-free.
// ---------------------------------------------------------------------------
#define QS_STRIDE 68
#define PS_STRIDE 68
#define KS_STRIDE 68
#define VS_STRIDE 72
#define SM_QS 0
#define SM_PS (128 * QS_STRIDE)
#define SM_KS (SM_PS + 128 * PS_STRIDE)
#define SM_VS (SM_KS + 64 * KS_STRIDE)
#define ATTN_SMEM_FLOATS (SM_VS + 64 * VS_STRIDE)
#define ATTN_SMEM_BYTES  (ATTN_SMEM_FLOATS * (int)sizeof(float))

__global__ __launch_bounds__(256) void attn_kernel(
    const float* __restrict__ q, const float* __restrict__ k,
    const float* __restrict__ v, float* __restrict__ ctx)
{
    extern __shared__ float sm[];
    float* Qs = sm + SM_QS;
    float* Ps = sm + SM_PS;
    float* Ks = sm + SM_KS;
    float* Vs = sm + SM_VS;

    int qt = blockIdx.x;            // q tile (128 rows)
    int bh = blockIdx.y;
    int b = bh >> 4;                // H = 16
    int h = bh & 15;
    int tid  = threadIdx.x;
    int lane = tid & 31;
    int warp = tid >> 5;            // owns q rows warp*16 .. +15
    int g   = lane >> 2;            // 0..7
    int tig = lane & 3;             // 0..3

    size_t base_col = (size_t)h * DKK;
    int s0 = b * SS + qt * 128;
    int kbase = b * SS;

    // Load Q tile (128x64), pre-scaled by 1/sqrt(DK)=0.125
#pragma unroll
    for (int i = 0; i < 8; i++) {
        int f = i * 256 + tid;          // float4 index
        int r = f >> 4;
        int c = (f & 15) * 4;
        float4 t4 = *(const float4*)(q + (size_t)(s0 + r) * DD + base_col + c);
        Qs[r * QS_STRIDE + c + 0] = t4.x * 0.125f;
        Qs[r * QS_STRIDE + c + 1] = t4.y * 0.125f;
        Qs[r * QS_STRIDE + c + 2] = t4.z * 0.125f;
        Qs[r * QS_STRIDE + c + 3] = t4.w * 0.125f;
    }

    // O accumulators: 8 d-tiles x 4 frags. Row g -> c0,c1; row g+8 -> c2,c3.
    float O[8][4];
    float m0 = -1e30f, m1 = -1e30f, l0 = 0.f, l1 = 0.f;
#pragma unroll
    for (int nt = 0; nt < 8; nt++)
#pragma unroll
        for (int c = 0; c < 4; c++) O[nt][c] = 0.f;

    int qrow = warp * 16;           // warp's m-tile base row in smem

    for (int kv0 = 0; kv0 < SS; kv0 += 64) {
        __syncthreads();   // prev-iter reads of Ks/Vs/Ps done; Q store visible

        // Load K (64x64 -> Ks) and V (64x64 -> Vs): 4 float4 each per thread
#pragma unroll
        for (int i = 0; i < 4; i++) {
            int f = i * 256 + tid;
            int r = f >> 4;
            int c = (f & 15) * 4;
            float4 kt = *(const float4*)(k + (size_t)(kbase + kv0 + r) * DD + base_col + c);
            Ks[r * KS_STRIDE + c + 0] = kt.x;
            Ks[r * KS_STRIDE + c + 1] = kt.y;
            Ks[r * KS_STRIDE + c + 2] = kt.z;
            Ks[r * KS_STRIDE + c + 3] = kt.w;
            float4 vt = *(const float4*)(v + (size_t)(kbase + kv0 + r) * DD + base_col + c);
            Vs[r * VS_STRIDE + c + 0] = vt.x;
            Vs[r * VS_STRIDE + c + 1] = vt.y;
            Vs[r * VS_STRIDE + c + 2] = vt.z;
            Vs[r * VS_STRIDE + c + 3] = vt.w;
        }
        __syncthreads();

        // S = (Q*scale) @ K^T : warp tile 16x64, 8 n-tiles, 8 k-steps (d=64)
        float s[8][4];
#pragma unroll
        for (int nt = 0; nt < 8; nt++)
#pragma unroll
            for (int c = 0; c < 4; c++) s[nt][c] = 0.f;

#pragma unroll
        for (int ks = 0; ks < 8; ks++) {
            int kk = ks * 8;
            unsigned a0 = __float_as_uint(Qs[(qrow + g    ) * QS_STRIDE + kk + tig    ]);
            unsigned a1 = __float_as_uint(Qs[(qrow + g + 8) * QS_STRIDE + kk + tig    ]);
            unsigned a2 = __float_as_uint(Qs[(qrow + g    ) * QS_STRIDE + kk + tig + 4]);
            unsigned a3 = __float_as_uint(Qs[(qrow + g + 8) * QS_STRIDE + kk + tig + 4]);
#pragma unroll
            for (int nt = 0; nt < 8; nt++) {
                unsigned b0 = __float_as_uint(Ks[(nt * 8 + g) * KS_STRIDE + kk + tig    ]);
                unsigned b1 = __float_as_uint(Ks[(nt * 8 + g) * KS_STRIDE + kk + tig + 4]);
                asm volatile(
                    "mma.sync.aligned.m16n8k8.row.col.f32.tf32.tf32.f32 "
                    "{%0,%1,%2,%3}, {%4,%5,%6,%7}, {%8,%9}, {%0,%1,%2,%3};"
                    : "+f"(s[nt][0]), "+f"(s[nt][1]), "+f"(s[nt][2]), "+f"(s[nt][3])
                    : "r"(a0), "r"(a1), "r"(a2), "r"(a3), "r"(b0), "r"(b1));
            }
        }

        // Online softmax. Row g holds s[nt][0..1], row g+8 holds s[nt][2..3].
        float rm0 = -1e30f, rm1 = -1e30f;
#pragma unroll
        for (int nt = 0; nt < 8; nt++) {
            rm0 = fmaxf(rm0, fmaxf(s[nt][0], s[nt][1]));
            rm1 = fmaxf(rm1, fmaxf(s[nt][2], s[nt][3]));
        }
#pragma unroll
        for (int o = 1; o < 4; o <<= 1) {
            rm0 = fmaxf(rm0, __shfl_xor_sync(0xffffffffu, rm0, o));
            rm1 = fmaxf(rm1, __shfl_xor_sync(0xffffffffu, rm1, o));
        }
        float mn0 = fmaxf(m0, rm0);
        float mn1 = fmaxf(m1, rm1);
        float corr0 = __expf(m0 - mn0);
        float corr1 = __expf(m1 - mn1);
        float ps0 = 0.f, ps1 = 0.f;
#pragma unroll
        for (int nt = 0; nt < 8; nt++) {
            s[nt][0] = __expf(s[nt][0] - mn0);
            s[nt][1] = __expf(s[nt][1] - mn0);
            s[nt][2] = __expf(s[nt][2] - mn1);
            s[nt][3] = __expf(s[nt][3] - mn1);
            ps0 += s[nt][0] + s[nt][1];
            ps1 += s[nt][2] + s[nt][3];
            // Store P in C-fragment positions
            float2 p01; p01.x = s[nt][0]; p01.y = s[nt][1];
            float2 p23; p23.x = s[nt][2]; p23.y = s[nt][3];
            *(float2*)&Ps[(qrow + g    ) * PS_STRIDE + nt * 8 + tig * 2] = p01;
            *(float2*)&Ps[(qrow + g + 8) * PS_STRIDE + nt * 8 + tig * 2] = p23;
        }
#pragma unroll
        for (int o = 1; o < 4; o <<= 1) {
            ps0 += __shfl_xor_sync(0xffffffffu, ps0, o);
            ps1 += __shfl_xor_sync(0xffffffffu, ps1, o);
        }
        l0 = l0 * corr0 + ps0;
        l1 = l1 * corr1 + ps1;
        m0 = mn0; m1 = mn1;
#pragma unroll
        for (int nt = 0; nt < 8; nt++) {
            O[nt][0] *= corr0; O[nt][1] *= corr0;
            O[nt][2] *= corr1; O[nt][3] *= corr1;
        }
        __syncthreads();   // Ps visible to own warp's mma path (plus smem fence)

        // O += P @ V : A = P (k=kv, 8 k-steps), B = V (n=d, 8 n-tiles)
#pragma unroll
        for (int ks = 0; ks < 8; ks++) {
            int kk = ks * 8;
            unsigned a0 = __float_as_uint(Ps[(qrow + g    ) * PS_STRIDE + kk + tig    ]);
            unsigned a1 = __float_as_uint(Ps[(qrow + g + 8) * PS_STRIDE + kk + tig    ]);
            unsigned a2 = __float_as_uint(Ps[(qrow + g    ) * PS_STRIDE + kk + tig + 4]);
            unsigned a3 = __float_as_uint(Ps[(qrow + g + 8) * PS_STRIDE + kk + tig + 4]);
#pragma unroll
            for (int nt = 0; nt < 8; nt++) {
                unsigned b0 = __float_as_uint(Vs[(kk + tig    ) * VS_STRIDE + nt * 8 + g]);
                unsigned b1 = __float_as_uint(Vs[(kk + tig + 4) * VS_STRIDE + nt * 8 + g]);
                asm volatile(
                    "mma.sync.aligned.m16n8k8.row.col.f32.tf32.tf32.f32 "
                    "{%0,%1,%2,%3}, {%4,%5,%6,%7}, {%8,%9}, {%0,%1,%2,%3};"
                    : "+f"(O[nt][0]), "+f"(O[nt][1]), "+f"(O[nt][2]), "+f"(O[nt][3])
                    : "r"(a0), "r"(a1), "r"(a2), "r"(a3), "r"(b0), "r"(b1));
            }
        }
    }

    // Normalize and write ctx[(b,s,h,d)]
    float inv0 = 1.f / l0;
    float inv1 = 1.f / l1;
    int r0 = s0 + warp * 16 + g;
#pragma unroll
    for (int nt = 0; nt < 8; nt++) {
        int c0 = nt * 8 + tig * 2;
        float2 o01; o01.x = O[nt][0] * inv0; o01.y = O[nt][1] * inv0;
        float2 o23; o23.x = O[nt][2] * inv1; o23.y = O[nt][3] * inv1;
        *(float2*)(ctx + (size_t)(r0    ) * DD + base_col + c0) = o01;
        *(float2*)(ctx + (size_t)(r0 + 8) * DD + base_col + c0) = o23;
    }
}

// ---------------------------------------------------------------------------
// Launch: ln1 -> Q,K,V gemms -> attention -> out-proj(+res) -> ln2 ->
//         ffn1(relu) -> ffn2(+res) -> d_out
// ---------------------------------------------------------------------------
extern "C" void kernel_launch(void* const* d_in, const int* in_sizes, int n_in,
                              void* d_out, int out_size)
{
    const float* x  = (const float*)d_in[0];
    // d_in[1] = src_mask (provably no effect in the reference; ignored)
    const float* Wq = (const float*)d_in[2];
    const float* bq = (const float*)d_in[3];
    const float* Wk = (const float*)d_in[4];
    const float* bk = (const float*)d_in[5];
    const float* Wv = (const float*)d_in[6];
    const float* bv = (const float*)d_in[7];
    const float* Wo = (const float*)d_in[8];
    const float* bo = (const float*)d_in[9];
    const float* W1 = (const float*)d_in[10];
    const float* b1 = (const float*)d_in[11];
    const float* W2 = (const float*)d_in[12];
    const float* b2 = (const float*)d_in[13];
    const float* a1 = (const float*)d_in[14];
    const float* g1 = (const float*)d_in[15];
    const float* a2 = (const float*)d_in[16];
    const float* g2 = (const float*)d_in[17];
    float* out = (float*)d_out;

    float *h, *q, *k, *v, *ctx, *x2, *h2, *ff;
    cudaGetSymbolAddress((void**)&h,   g_h);
    cudaGetSymbolAddress((void**)&q,   g_q);
    cudaGetSymbolAddress((void**)&k,   g_k);
    cudaGetSymbolAddress((void**)&v,   g_v);
    cudaGetSymbolAddress((void**)&ctx, g_ctx);
    cudaGetSymbolAddress((void**)&x2,  g_x2);
    cudaGetSymbolAddress((void**)&h2,  g_h2);
    cudaGetSymbolAddress((void**)&ff,  g_ff);

    cudaFuncSetAttribute(attn_kernel,
                         cudaFuncAttributeMaxDynamicSharedMemorySize,
                         ATTN_SMEM_BYTES);

    dim3 gD(DD / 128, MROWS / 128);      // (8, 32)
    dim3 gF(DFFN / 128, MROWS / 128);    // (32, 32)

    // ln1
    ln_kernel<<<MROWS, 256>>>(x, h, a1, g1);
    // Q, K, V projections (tf32 tensor core)
    tf32_gemm<false, false><<<gD, 256>>>(h, Wq, bq, nullptr, q, MROWS, DD, DD);
    tf32_gemm<false, false><<<gD, 256>>>(h, Wk, bk, nullptr, k, MROWS, DD, DD);
    tf32_gemm<false, false><<<gD, 256>>>(h, Wv, bv, nullptr, v, MROWS, DD, DD);
    // attention (tf32 mma flash)
    attn_kernel<<<dim3(SS / 128, BB * HH), 256, ATTN_SMEM_BYTES>>>(q, k, v, ctx);
    // out-proj + residual: x2 = x + ctx@Wo + bo
    tf32_gemm<false, true><<<gD, 256>>>(ctx, Wo, bo, x, x2, MROWS, DD, DD);
    // ln2
    ln_kernel<<<MROWS, 256>>>(x2, h2, a2, g2);
    // ffn1 with relu
    tf32_gemm<true, false><<<gF, 256>>>(h2, W1, b1, nullptr, ff, MROWS, DFFN, DD);
    // ffn2 + residual -> output
    tf32_gemm<false, true><<<gD, 256>>>(ff, W2, b2, x2, out, MROWS, DD, DFFN);
}

// round 6
// speedup vs baseline: 1.0576x; 1.0576x over previous
#include <cuda_runtime.h>
#include <cstdint>
#include <math.h>

// Problem shape (fixed by the reference)
#define BB    2
#define SS    2048
#define DD    1024
#define HH    16
#define DKK   64
#define DFFN  4096
#define MROWS (BB*SS)   // 4096 token rows

// ---------------------------------------------------------------------------
// Scratch (device globals: allocation inside kernel_launch is forbidden)
// ---------------------------------------------------------------------------
__device__ float g_h  [MROWS*DD];    // ln1(x), tf32-rounded
__device__ float g_q  [MROWS*DD];
__device__ float g_k  [MROWS*DD];
__device__ float g_v  [MROWS*DD];
__device__ float g_ctx[MROWS*DD];    // attention context (tf32-rounded)
__device__ float g_x2 [MROWS*DD];    // x + attn out-proj (exact)
__device__ float g_h2 [MROWS*DD];    // ln2(x2), tf32-rounded
__device__ float g_ff [MROWS*DFFN];  // relu(h2@W1+b1), tf32-rounded
// Transposed + tf32-rounded weights (B operands, n-major for ldmatrix)
__device__ float g_wtq[DD*DD];
__device__ float g_wtk[DD*DD];
__device__ float g_wtv[DD*DD];
__device__ float g_wto[DD*DD];
__device__ float g_wt1[DD*DFFN];     // [DFF][D]
__device__ float g_wt2[DD*DFFN];     // [D][DFF]

__device__ __forceinline__ unsigned f2tf32(float x) {
    unsigned u;
    asm("cvt.rna.tf32.f32 %0, %1;" : "=r"(u) : "f"(x));
    return u;
}
__device__ __forceinline__ float roundtf(float x) {
    return __uint_as_float(f2tf32(x));
}

#define CP_ASYNC16(dst, src) \
    asm volatile("cp.async.cg.shared.global [%0], [%1], 16;\n" :: "r"(dst), "l"(src))

// ---------------------------------------------------------------------------
// Weight prep: dst[C][R] = round_tf32(src[R][C])  (transpose + round)
// Block (32,8), grid (C/32, R/32).
// ---------------------------------------------------------------------------
__global__ __launch_bounds__(256) void transpose_round(
    const float* __restrict__ src, float* __restrict__ dst, int R, int Ccols)
{
    __shared__ float tile[32][33];
    int c0 = blockIdx.x * 32, r0 = blockIdx.y * 32;
    int tx = threadIdx.x, ty = threadIdx.y;
#pragma unroll
    for (int i = ty; i < 32; i += 8)
        tile[i][tx] = src[(size_t)(r0 + i) * Ccols + c0 + tx];
    __syncthreads();
#pragma unroll
    for (int i = ty; i < 32; i += 8)
        dst[(size_t)(c0 + i) * R + r0 + tx] = roundtf(tile[tx][i]);
}

// ---------------------------------------------------------------------------
// LayerNorm: alpha * (x - mean) / (std_ddof1 + eps) + beta, output tf32-rounded
// ---------------------------------------------------------------------------
__global__ __launch_bounds__(256) void ln_kernel(
    const float* __restrict__ x, float* __restrict__ out,
    const float* __restrict__ pa, const float* __restrict__ pg)
{
    int row = blockIdx.x;
    int t   = threadIdx.x;
    const float4* xr = (const float4*)(x + (size_t)row * DD);
    float4 v = xr[t];
    float s  = v.x + v.y + v.z + v.w;
    float sq = v.x*v.x + v.y*v.y + v.z*v.z + v.w*v.w;
#pragma unroll
    for (int o = 16; o > 0; o >>= 1) {
        s  += __shfl_xor_sync(0xffffffffu, s,  o);
        sq += __shfl_xor_sync(0xffffffffu, sq, o);
    }
    __shared__ float rs[8], rq[8];
    __shared__ float s_mean, s_inv;
    int w = t >> 5, lane = t & 31;
    if (lane == 0) { rs[w] = s; rq[w] = sq; }
    __syncthreads();
    if (t == 0) {
        float ts = 0.f, tq = 0.f;
#pragma unroll
        for (int i = 0; i < 8; i++) { ts += rs[i]; tq += rq[i]; }
        float mean = ts / (float)DD;
        float var  = (tq - (float)DD * mean * mean) / (float)(DD - 1);
        float stdv = sqrtf(fmaxf(var, 0.f));
        s_mean = mean;
        s_inv  = 1.f / (stdv + 1e-6f);
    }
    __syncthreads();
    float a = *pa, g = *pg;
    float mean = s_mean, inv = s_inv;
    float4 o;
    o.x = roundtf(a * (v.x - mean) * inv + g);
    o.y = roundtf(a * (v.y - mean) * inv + g);
    o.z = roundtf(a * (v.z - mean) * inv + g);
    o.w = roundtf(a * (v.w - mean) * inv + g);
    ((float4*)(out + (size_t)row * DD))[t] = o;
}

// ---------------------------------------------------------------------------
// TF32 tensor-core GEMM: C[M,N] = A[M,K] @ Wt[N,K]^T + bias (+relu)(+res)
// A row-major [M,K]; Wt is the PRE-TRANSPOSED weight [N,K] (k contiguous).
// Block 128x128, 128 threads = 4 warps (2m x 2n), warp tile 64x64.
// cp.async double-buffered BK=16; fragments via ldmatrix.b16 (tf32 trick).
// Operands are pre-rounded to tf32 by producers, so HW truncation is exact.
// Epilogue rounds output to tf32 when !RES (it feeds a later GEMM A operand).
// ---------------------------------------------------------------------------
#define AST 20                       // smem row stride in floats
#define STG_BYTES (128*AST*4)        // 10240 per stage

template<bool RELU, bool RES>
__global__ __launch_bounds__(128) void tf32_gemm(
    const float* __restrict__ A, const float* __restrict__ Wt,
    const float* __restrict__ bias, const float* __restrict__ res,
    float* __restrict__ C, int M, int N, int K)
{
    __shared__ __align__(16) float As[2][128*AST];
    __shared__ __align__(16) float Bs[2][128*AST];

    int bn = blockIdx.x * 128, bm = blockIdx.y * 128;
    int tid = threadIdx.x, lane = tid & 31, warp = tid >> 5;
    int wm = warp & 1, wn = warp >> 1;

    float acc[4][8][4] = {};

    // cp.async thread mapping: 4 rows (tid>>2 + 32i), one 16B chunk (tid&3)
    int ldRow   = tid >> 2;
    int ldChunk = (tid & 3) * 4;
    const float* aG = A  + (size_t)(bm + ldRow) * K + ldChunk;
    const float* bG = Wt + (size_t)(bn + ldRow) * K + ldChunk;
    unsigned aS = (unsigned)__cvta_generic_to_shared(&As[0][0]) + (unsigned)(ldRow*AST + ldChunk)*4u;
    unsigned bS = (unsigned)__cvta_generic_to_shared(&Bs[0][0]) + (unsigned)(ldRow*AST + ldChunk)*4u;

    // ldmatrix per-thread base addresses (stage 0)
    // A tiles: rows m0+(lane&15), col (lane>=16 ? 4 : 0)
    unsigned aF = (unsigned)__cvta_generic_to_shared(&As[0][0])
                + (unsigned)(((wm*64 + (lane & 15)) * AST + ((lane >> 4) << 2)) * 4);
    // B tiles: rows n0+(lane&7)+(lane>=16?8:0), col (lane&8 ? 4 : 0)
    unsigned bF = (unsigned)__cvta_generic_to_shared(&Bs[0][0])
                + (unsigned)(((wn*64 + (lane & 7) + ((lane & 16) >> 1)) * AST + ((lane & 8) >> 1)) * 4);

    int nIt = K >> 4;

    // Prologue: stage 0
#pragma unroll
    for (int i = 0; i < 4; i++) {
        CP_ASYNC16(aS + i*32*AST*4, aG + (size_t)i*32*K);
        CP_ASYNC16(bS + i*32*AST*4, bG + (size_t)i*32*K);
    }
    asm volatile("cp.async.commit_group;\n" ::);

    for (int it = 0; it < nIt; it++) {
        int cur = it & 1;
        if (it + 1 < nIt) {
            int nxt = cur ^ 1;
            const float* aGn = aG + (it + 1) * 16;
            const float* bGn = bG + (it + 1) * 16;
            unsigned aSn = aS + (unsigned)nxt * STG_BYTES;
            unsigned bSn = bS + (unsigned)nxt * STG_BYTES;
#pragma unroll
            for (int i = 0; i < 4; i++) {
                CP_ASYNC16(aSn + i*32*AST*4, aGn + (size_t)i*32*K);
                CP_ASYNC16(bSn + i*32*AST*4, bGn + (size_t)i*32*K);
            }
        }
        asm volatile("cp.async.commit_group;\n" ::);
        asm volatile("cp.async.wait_group 1;\n" ::);
        __syncthreads();

        unsigned aFs = aF + (unsigned)cur * STG_BYTES;
        unsigned bFs = bF + (unsigned)cur * STG_BYTES;
#pragma unroll
        for (int ks = 0; ks < 2; ks++) {
            unsigned a[4][4], b[4][4];
#pragma unroll
            for (int mt = 0; mt < 4; mt++)
                asm volatile(
                    "ldmatrix.sync.aligned.m8n8.x4.shared.b16 {%0,%1,%2,%3}, [%4];"
                    : "=r"(a[mt][0]), "=r"(a[mt][1]), "=r"(a[mt][2]), "=r"(a[mt][3])
                    : "r"(aFs + (unsigned)(mt * (16*AST*4) + ks * 32)));
#pragma unroll
            for (int np = 0; np < 4; np++)
                asm volatile(
                    "ldmatrix.sync.aligned.m8n8.x4.shared.b16 {%0,%1,%2,%3}, [%4];"
                    : "=r"(b[np][0]), "=r"(b[np][1]), "=r"(b[np][2]), "=r"(b[np][3])
                    : "r"(bFs + (unsigned)(np * (16*AST*4) + ks * 32)));
#pragma unroll
            for (int mt = 0; mt < 4; mt++)
#pragma unroll
                for (int np = 0; np < 4; np++) {
                    asm volatile(
                        "mma.sync.aligned.m16n8k8.row.col.f32.tf32.tf32.f32 "
                        "{%0,%1,%2,%3}, {%4,%5,%6,%7}, {%8,%9}, {%0,%1,%2,%3};"
                        : "+f"(acc[mt][2*np][0]), "+f"(acc[mt][2*np][1]),
                          "+f"(acc[mt][2*np][2]), "+f"(acc[mt][2*np][3])
                        : "r"(a[mt][0]), "r"(a[mt][1]), "r"(a[mt][2]), "r"(a[mt][3]),
                          "r"(b[np][0]), "r"(b[np][1]));
                    asm volatile(
                        "mma.sync.aligned.m16n8k8.row.col.f32.tf32.tf32.f32 "
                        "{%0,%1,%2,%3}, {%4,%5,%6,%7}, {%8,%9}, {%0,%1,%2,%3};"
                        : "+f"(acc[mt][2*np+1][0]), "+f"(acc[mt][2*np+1][1]),
                          "+f"(acc[mt][2*np+1][2]), "+f"(acc[mt][2*np+1][3])
                        : "r"(a[mt][0]), "r"(a[mt][1]), "r"(a[mt][2]), "r"(a[mt][3]),
                          "r"(b[np][2]), "r"(b[np][3]));
                }
        }
        __syncthreads();
    }

    // Epilogue
    int g = lane >> 2, tg = lane & 3;
#pragma unroll
    for (int mt = 0; mt < 4; mt++) {
        int m0 = bm + wm*64 + mt*16 + g;
#pragma unroll
        for (int nt = 0; nt < 8; nt++) {
            int n0 = bn + wn*64 + nt*8 + tg*2;
            float bx = bias[n0], by = bias[n0 + 1];
#pragma unroll
            for (int hf = 0; hf < 2; hf++) {
                int m = m0 + hf*8;
                float rx = acc[mt][nt][hf*2 + 0] + bx;
                float ry = acc[mt][nt][hf*2 + 1] + by;
                if (RELU) { rx = fmaxf(rx, 0.f); ry = fmaxf(ry, 0.f); }
                size_t off = (size_t)m * N + n0;
                if (RES) {
                    float2 rr = *(const float2*)(res + off);
                    rx += rr.x; ry += rr.y;
                } else {
                    rx = roundtf(rx);
                    ry = roundtf(ry);
                }
                float2 o2; o2.x = rx; o2.y = ry;
                *(float2*)(C + off) = o2;
            }
        }
    }
}

// ---------------------------------------------------------------------------
// Fused flash attention with tf32 mma (mask is a no-op in the reference).
// Block: 256 threads = 8 warps. Tile: 128 q-rows x 64 kv per block.
// smem floats: Qs[128][68] | Ps[128][68] | Ks[64][68] | Vs[64][72]
// ---------------------------------------------------------------------------
#define QS_STRIDE 68
#define PS_STRIDE 68
#define KS_STRIDE 68
#define VS_STRIDE 72
#define SM_QS 0
#define SM_PS (128 * QS_STRIDE)
#define SM_KS (SM_PS + 128 * PS_STRIDE)
#define SM_VS (SM_KS + 64 * KS_STRIDE)
#define ATTN_SMEM_FLOATS (SM_VS + 64 * VS_STRIDE)
#define ATTN_SMEM_BYTES  (ATTN_SMEM_FLOATS * (int)sizeof(float))

__global__ __launch_bounds__(256) void attn_kernel(
    const float* __restrict__ q, const float* __restrict__ k,
    const float* __restrict__ v, float* __restrict__ ctx)
{
    extern __shared__ float sm[];
    float* Qs = sm + SM_QS;
    float* Ps = sm + SM_PS;
    float* Ks = sm + SM_KS;
    float* Vs = sm + SM_VS;

    int qt = blockIdx.x;
    int bh = blockIdx.y;
    int b = bh >> 4;
    int h = bh & 15;
    int tid  = threadIdx.x;
    int lane = tid & 31;
    int warp = tid >> 5;
    int g   = lane >> 2;
    int tig = lane & 3;

    size_t base_col = (size_t)h * DKK;
    int s0 = b * SS + qt * 128;
    int kbase = b * SS;

#pragma unroll
    for (int i = 0; i < 8; i++) {
        int f = i * 256 + tid;
        int r = f >> 4;
        int c = (f & 15) * 4;
        float4 t4 = *(const float4*)(q + (size_t)(s0 + r) * DD + base_col + c);
        Qs[r * QS_STRIDE + c + 0] = t4.x * 0.125f;
        Qs[r * QS_STRIDE + c + 1] = t4.y * 0.125f;
        Qs[r * QS_STRIDE + c + 2] = t4.z * 0.125f;
        Qs[r * QS_STRIDE + c + 3] = t4.w * 0.125f;
    }

    float O[8][4];
    float m0 = -1e30f, m1 = -1e30f, l0 = 0.f, l1 = 0.f;
#pragma unroll
    for (int nt = 0; nt < 8; nt++)
#pragma unroll
        for (int c = 0; c < 4; c++) O[nt][c] = 0.f;

    int qrow = warp * 16;

    for (int kv0 = 0; kv0 < SS; kv0 += 64) {
        __syncthreads();
#pragma unroll
        for (int i = 0; i < 4; i++) {
            int f = i * 256 + tid;
            int r = f >> 4;
            int c = (f & 15) * 4;
            float4 kt = *(const float4*)(k + (size_t)(kbase + kv0 + r) * DD + base_col + c);
            Ks[r * KS_STRIDE + c + 0] = kt.x;
            Ks[r * KS_STRIDE + c + 1] = kt.y;
            Ks[r * KS_STRIDE + c + 2] = kt.z;
            Ks[r * KS_STRIDE + c + 3] = kt.w;
            float4 vt = *(const float4*)(v + (size_t)(kbase + kv0 + r) * DD + base_col + c);
            Vs[r * VS_STRIDE + c + 0] = vt.x;
            Vs[r * VS_STRIDE + c + 1] = vt.y;
            Vs[r * VS_STRIDE + c + 2] = vt.z;
            Vs[r * VS_STRIDE + c + 3] = vt.w;
        }
        __syncthreads();

        float s[8][4];
#pragma unroll
        for (int nt = 0; nt < 8; nt++)
#pragma unroll
            for (int c = 0; c < 4; c++) s[nt][c] = 0.f;

#pragma unroll
        for (int ks = 0; ks < 8; ks++) {
            int kk = ks * 8;
            unsigned a0 = __float_as_uint(Qs[(qrow + g    ) * QS_STRIDE + kk + tig    ]);
            unsigned a1 = __float_as_uint(Qs[(qrow + g + 8) * QS_STRIDE + kk + tig    ]);
            unsigned a2 = __float_as_uint(Qs[(qrow + g    ) * QS_STRIDE + kk + tig + 4]);
            unsigned a3 = __float_as_uint(Qs[(qrow + g + 8) * QS_STRIDE + kk + tig + 4]);
#pragma unroll
            for (int nt = 0; nt < 8; nt++) {
                unsigned b0 = __float_as_uint(Ks[(nt * 8 + g) * KS_STRIDE + kk + tig    ]);
                unsigned b1 = __float_as_uint(Ks[(nt * 8 + g) * KS_STRIDE + kk + tig + 4]);
                asm volatile(
                    "mma.sync.aligned.m16n8k8.row.col.f32.tf32.tf32.f32 "
                    "{%0,%1,%2,%3}, {%4,%5,%6,%7}, {%8,%9}, {%0,%1,%2,%3};"
                    : "+f"(s[nt][0]), "+f"(s[nt][1]), "+f"(s[nt][2]), "+f"(s[nt][3])
                    : "r"(a0), "r"(a1), "r"(a2), "r"(a3), "r"(b0), "r"(b1));
            }
        }

        float rm0 = -1e30f, rm1 = -1e30f;
#pragma unroll
        for (int nt = 0; nt < 8; nt++) {
            rm0 = fmaxf(rm0, fmaxf(s[nt][0], s[nt][1]));
            rm1 = fmaxf(rm1, fmaxf(s[nt][2], s[nt][3]));
        }
#pragma unroll
        for (int o = 1; o < 4; o <<= 1) {
            rm0 = fmaxf(rm0, __shfl_xor_sync(0xffffffffu, rm0, o));
            rm1 = fmaxf(rm1, __shfl_xor_sync(0xffffffffu, rm1, o));
        }
        float mn0 = fmaxf(m0, rm0);
        float mn1 = fmaxf(m1, rm1);
        float corr0 = __expf(m0 - mn0);
        float corr1 = __expf(m1 - mn1);
        float ps0 = 0.f, ps1 = 0.f;
#pragma unroll
        for (int nt = 0; nt < 8; nt++) {
            s[nt][0] = __expf(s[nt][0] - mn0);
            s[nt][1] = __expf(s[nt][1] - mn0);
            s[nt][2] = __expf(s[nt][2] - mn1);
            s[nt][3] = __expf(s[nt][3] - mn1);
            ps0 += s[nt][0] + s[nt][1];
            ps1 += s[nt][2] + s[nt][3];
            float2 p01; p01.x = s[nt][0]; p01.y = s[nt][1];
            float2 p23; p23.x = s[nt][2]; p23.y = s[nt][3];
            *(float2*)&Ps[(qrow + g    ) * PS_STRIDE + nt * 8 + tig * 2] = p01;
            *(float2*)&Ps[(qrow + g + 8) * PS_STRIDE + nt * 8 + tig * 2] = p23;
        }
#pragma unroll
        for (int o = 1; o < 4; o <<= 1) {
            ps0 += __shfl_xor_sync(0xffffffffu, ps0, o);
            ps1 += __shfl_xor_sync(0xffffffffu, ps1, o);
        }
        l0 = l0 * corr0 + ps0;
        l1 = l1 * corr1 + ps1;
        m0 = mn0; m1 = mn1;
#pragma unroll
        for (int nt = 0; nt < 8; nt++) {
            O[nt][0] *= corr0; O[nt][1] *= corr0;
            O[nt][2] *= corr1; O[nt][3] *= corr1;
        }
        __syncthreads();

#pragma unroll
        for (int ks = 0; ks < 8; ks++) {
            int kk = ks * 8;
            unsigned a0 = __float_as_uint(Ps[(qrow + g    ) * PS_STRIDE + kk + tig    ]);
            unsigned a1 = __float_as_uint(Ps[(qrow + g + 8) * PS_STRIDE + kk + tig    ]);
            unsigned a2 = __float_as_uint(Ps[(qrow + g    ) * PS_STRIDE + kk + tig + 4]);
            unsigned a3 = __float_as_uint(Ps[(qrow + g + 8) * PS_STRIDE + kk + tig + 4]);
#pragma unroll
            for (int nt = 0; nt < 8; nt++) {
                unsigned b0 = __float_as_uint(Vs[(kk + tig    ) * VS_STRIDE + nt * 8 + g]);
                unsigned b1 = __float_as_uint(Vs[(kk + tig + 4) * VS_STRIDE + nt * 8 + g]);
                asm volatile(
                    "mma.sync.aligned.m16n8k8.row.col.f32.tf32.tf32.f32 "
                    "{%0,%1,%2,%3}, {%4,%5,%6,%7}, {%8,%9}, {%0,%1,%2,%3};"
                    : "+f"(O[nt][0]), "+f"(O[nt][1]), "+f"(O[nt][2]), "+f"(O[nt][3])
                    : "r"(a0), "r"(a1), "r"(a2), "r"(a3), "r"(b0), "r"(b1));
            }
        }
    }

    float inv0 = 1.f / l0;
    float inv1 = 1.f / l1;
    int r0 = s0 + warp * 16 + g;
#pragma unroll
    for (int nt = 0; nt < 8; nt++) {
        int c0 = nt * 8 + tig * 2;
        float2 o01; o01.x = roundtf(O[nt][0] * inv0); o01.y = roundtf(O[nt][1] * inv0);
        float2 o23; o23.x = roundtf(O[nt][2] * inv1); o23.y = roundtf(O[nt][3] * inv1);
        *(float2*)(ctx + (size_t)(r0    ) * DD + base_col + c0) = o01;
        *(float2*)(ctx + (size_t)(r0 + 8) * DD + base_col + c0) = o23;
    }
}

// ---------------------------------------------------------------------------
// Launch
// ---------------------------------------------------------------------------
extern "C" void kernel_launch(void* const* d_in, const int* in_sizes, int n_in,
                              void* d_out, int out_size)
{
    const float* x  = (const float*)d_in[0];
    // d_in[1] = src_mask (provably no effect in the reference; ignored)
    const float* Wq = (const float*)d_in[2];
    const float* bq = (const float*)d_in[3];
    const float* Wk = (const float*)d_in[4];
    const float* bk = (const float*)d_in[5];
    const float* Wv = (const float*)d_in[6];
    const float* bv = (const float*)d_in[7];
    const float* Wo = (const float*)d_in[8];
    const float* bo = (const float*)d_in[9];
    const float* W1 = (const float*)d_in[10];
    const float* b1 = (const float*)d_in[11];
    const float* W2 = (const float*)d_in[12];
    const float* b2 = (const float*)d_in[13];
    const float* a1 = (const float*)d_in[14];
    const float* g1 = (const float*)d_in[15];
    const float* a2 = (const float*)d_in[16];
    const float* g2 = (const float*)d_in[17];
    float* out = (float*)d_out;

    float *h, *q, *k, *v, *ctx, *x2, *h2, *ff;
    float *wtq, *wtk, *wtv, *wto, *wt1, *wt2;
    cudaGetSymbolAddress((void**)&h,   g_h);
    cudaGetSymbolAddress((void**)&q,   g_q);
    cudaGetSymbolAddress((void**)&k,   g_k);
    cudaGetSymbolAddress((void**)&v,   g_v);
    cudaGetSymbolAddress((void**)&ctx, g_ctx);
    cudaGetSymbolAddress((void**)&x2,  g_x2);
    cudaGetSymbolAddress((void**)&h2,  g_h2);
    cudaGetSymbolAddress((void**)&ff,  g_ff);
    cudaGetSymbolAddress((void**)&wtq, g_wtq);
    cudaGetSymbolAddress((void**)&wtk, g_wtk);
    cudaGetSymbolAddress((void**)&wtv, g_wtv);
    cudaGetSymbolAddress((void**)&wto, g_wto);
    cudaGetSymbolAddress((void**)&wt1, g_wt1);
    cudaGetSymbolAddress((void**)&wt2, g_wt2);

    cudaFuncSetAttribute(attn_kernel,
                         cudaFuncAttributeMaxDynamicSharedMemorySize,
                         ATTN_SMEM_BYTES);

    dim3 tb(32, 8);
    // Weight prep: W[K][N] -> Wt[N][K], tf32-rounded
    transpose_round<<<dim3(DD/32,   DD/32), tb>>>(Wq, wtq, DD, DD);
    transpose_round<<<dim3(DD/32,   DD/32), tb>>>(Wk, wtk, DD, DD);
    transpose_round<<<dim3(DD/32,   DD/32), tb>>>(Wv, wtv, DD, DD);
    transpose_round<<<dim3(DD/32,   DD/32), tb>>>(Wo, wto, DD, DD);
    transpose_round<<<dim3(DFFN/32, DD/32), tb>>>(W1, wt1, DD, DFFN);
    transpose_round<<<dim3(DD/32, DFFN/32), tb>>>(W2, wt2, DFFN, DD);

    dim3 gD(DD / 128, MROWS / 128);      // (8, 32)
    dim3 gF(DFFN / 128, MROWS / 128);    // (32, 32)

    ln_kernel<<<MROWS, 256>>>(x, h, a1, g1);
    tf32_gemm<false, false><<<gD, 128>>>(h, wtq, bq, nullptr, q, MROWS, DD, DD);
    tf32_gemm<false, false><<<gD, 128>>>(h, wtk, bk, nullptr, k, MROWS, DD, DD);
    tf32_gemm<false, false><<<gD, 128>>>(h, wtv, bv, nullptr, v, MROWS, DD, DD);
    attn_kernel<<<dim3(SS / 128, BB * HH), 256, ATTN_SMEM_BYTES>>>(q, k, v, ctx);
    tf32_gemm<false, true><<<gD, 128>>>(ctx, wto, bo, x, x2, MROWS, DD, DD);
    ln_kernel<<<MROWS, 256>>>(x2, h2, a2, g2);
    tf32_gemm<true, false><<<gF, 128>>>(h2, wt1, b1, nullptr, ff, MROWS, DFFN, DD);
    tf32_gemm<false, true><<<gD, 128>>>(ff, wt2, b2, x2, out, MROWS, DD, DFFN);
}

// round 8
// speedup vs baseline: 1.2073x; 1.1415x over previous
#include <cuda_runtime.h>
#include <cstdint>
#include <math.h>

// Problem shape (fixed by the reference)
#define BB    2
#define SS    2048
#define DD    1024
#define HH    16
#define DKK   64
#define DFFN  4096
#define MROWS (BB*SS)   // 4096 token rows

// ---------------------------------------------------------------------------
// Scratch (device globals: allocation inside kernel_launch is forbidden)
// ---------------------------------------------------------------------------
__device__ float g_h  [MROWS*DD];    // ln1(x), tf32-rounded
__device__ float g_q  [MROWS*DD];
__device__ float g_k  [MROWS*DD];
__device__ float g_v  [MROWS*DD];
__device__ float g_ctx[MROWS*DD];    // attention context (tf32-rounded)
__device__ float g_x2 [MROWS*DD];    // x + attn out-proj (exact)
__device__ float g_h2 [MROWS*DD];    // ln2(x2), tf32-rounded
__device__ float g_ff [MROWS*DFFN];  // relu(h2@W1+b1), tf32-rounded
// Transposed + tf32-rounded weights (B operands, n-major for ldmatrix)
__device__ float g_wtq[DD*DD];
__device__ float g_wtk[DD*DD];
__device__ float g_wtv[DD*DD];
__device__ float g_wto[DD*DD];
__device__ float g_wt1[DD*DFFN];     // [DFF][D]
__device__ float g_wt2[DD*DFFN];     // [D][DFF]

__device__ __forceinline__ unsigned f2tf32(float x) {
    unsigned u;
    asm("cvt.rna.tf32.f32 %0, %1;" : "=r"(u) : "f"(x));
    return u;
}
__device__ __forceinline__ float roundtf(float x) {
    return __uint_as_float(f2tf32(x));
}

#define CP_ASYNC16(dst, src) \
    asm volatile("cp.async.cg.shared.global [%0], [%1], 16;\n" :: "r"(dst), "l"(src))

// ---------------------------------------------------------------------------
// Batched weight prep, 2 launches total.
// transpose_round4: the four D x D weights in one launch (grid 4096).
// transpose_round_ffn: W1 [D][DFF] and W2 [DFF][D] in one launch (grid 8192).
// dst[C][R] = round_tf32(src[R][C]). Block: 256 threads (32x8 logical).
// ---------------------------------------------------------------------------
__global__ __launch_bounds__(256) void transpose_round4(
    const float* __restrict__ s0, const float* __restrict__ s1,
    const float* __restrict__ s2, const float* __restrict__ s3,
    float* __restrict__ d0, float* __restrict__ d1,
    float* __restrict__ d2, float* __restrict__ d3)
{
    __shared__ float tile[32][33];
    int id = blockIdx.x;
    int w = id >> 10, t = id & 1023;
    const float* src = (w == 0) ? s0 : (w == 1) ? s1 : (w == 2) ? s2 : s3;
    float*       dst = (w == 0) ? d0 : (w == 1) ? d1 : (w == 2) ? d2 : d3;
    int c0 = (t & 31) * 32, r0 = (t >> 5) * 32;
    int tx = threadIdx.x & 31, ty = threadIdx.x >> 5;
#pragma unroll
    for (int i = ty; i < 32; i += 8)
        tile[i][tx] = src[(size_t)(r0 + i) * DD + c0 + tx];
    __syncthreads();
#pragma unroll
    for (int i = ty; i < 32; i += 8)
        dst[(size_t)(c0 + i) * DD + r0 + tx] = roundtf(tile[tx][i]);
}

__global__ __launch_bounds__(256) void transpose_round_ffn(
    const float* __restrict__ W1, const float* __restrict__ W2,
    float* __restrict__ wt1, float* __restrict__ wt2)
{
    __shared__ float tile[32][33];
    int id = blockIdx.x;
    const float* src; float* dst; int R, C, tr, tc;
    if (id < 4096) { src = W1; dst = wt1; R = DD;   C = DFFN; tc = id & 127; tr = id >> 7; }
    else { int t = id - 4096; src = W2; dst = wt2; R = DFFN; C = DD;   tc = t & 31;  tr = t >> 5; }
    int c0 = tc * 32, r0 = tr * 32;
    int tx = threadIdx.x & 31, ty = threadIdx.x >> 5;
#pragma unroll
    for (int i = ty; i < 32; i += 8)
        tile[i][tx] = src[(size_t)(r0 + i) * C + c0 + tx];
    __syncthreads();
#pragma unroll
    for (int i = ty; i < 32; i += 8)
        dst[(size_t)(c0 + i) * R + r0 + tx] = roundtf(tile[tx][i]);
}

// ---------------------------------------------------------------------------
// LayerNorm: alpha * (x - mean) / (std_ddof1 + eps) + beta, output tf32-rounded
// ---------------------------------------------------------------------------
__global__ __launch_bounds__(256) void ln_kernel(
    const float* __restrict__ x, float* __restrict__ out,
    const float* __restrict__ pa, const float* __restrict__ pg)
{
    int row = blockIdx.x;
    int t   = threadIdx.x;
    const float4* xr = (const float4*)(x + (size_t)row * DD);
    float4 v = xr[t];
    float s  = v.x + v.y + v.z + v.w;
    float sq = v.x*v.x + v.y*v.y + v.z*v.z + v.w*v.w;
#pragma unroll
    for (int o = 16; o > 0; o >>= 1) {
        s  += __shfl_xor_sync(0xffffffffu, s,  o);
        sq += __shfl_xor_sync(0xffffffffu, sq, o);
    }
    __shared__ float rs[8], rq[8];
    __shared__ float s_mean, s_inv;
    int w = t >> 5, lane = t & 31;
    if (lane == 0) { rs[w] = s; rq[w] = sq; }
    __syncthreads();
    if (t == 0) {
        float ts = 0.f, tq = 0.f;
#pragma unroll
        for (int i = 0; i < 8; i++) { ts += rs[i]; tq += rq[i]; }
        float mean = ts / (float)DD;
        float var  = (tq - (float)DD * mean * mean) / (float)(DD - 1);
        float stdv = sqrtf(fmaxf(var, 0.f));
        s_mean = mean;
        s_inv  = 1.f / (stdv + 1e-6f);
    }
    __syncthreads();
    float a = *pa, g = *pg;
    float mean = s_mean, inv = s_inv;
    float4 o;
    o.x = roundtf(a * (v.x - mean) * inv + g);
    o.y = roundtf(a * (v.y - mean) * inv + g);
    o.z = roundtf(a * (v.z - mean) * inv + g);
    o.w = roundtf(a * (v.w - mean) * inv + g);
    ((float4*)(out + (size_t)row * DD))[t] = o;
}

// ---------------------------------------------------------------------------
// TF32 tensor-core GEMM: C[M,N] = A[M,K] @ Wt[N,K]^T + bias (+relu)(+res)
// A row-major [M,K]; Wt is the PRE-TRANSPOSED weight [N,K] (k contiguous).
// Block 128x128, 256 threads = 8 warps (2m x 4n), warp tile 64x32.
// 3-stage cp.async pipeline, BK=16; fragments via ldmatrix.b16 (tf32 trick);
// single __syncthreads per iteration. Operands pre-rounded to tf32 by
// producers. Epilogue rounds output to tf32 when !RES.
// ---------------------------------------------------------------------------
#define AST 20                        // smem row stride in floats
#define STG_FLOATS (128*AST)          // 2560 per matrix per stage
#define STG_BYTES  (STG_FLOATS*4)     // 10240
#define GEMM_SMEM  (3*2*STG_BYTES)    // 61440 B (3 stages x (A,B))

template<bool RELU, bool RES>
__global__ __launch_bounds__(256, 2) void tf32_gemm(
    const float* __restrict__ A, const float* __restrict__ Wt,
    const float* __restrict__ bias, const float* __restrict__ res,
    float* __restrict__ C, int M, int N, int K)
{
    extern __shared__ float smg[];   // stage s: A at s*2*STG, B at s*2*STG+STG

    int bn = blockIdx.x * 128, bm = blockIdx.y * 128;
    int tid = threadIdx.x, lane = tid & 31, warp = tid >> 5;
    int wm = warp & 1, wn = warp >> 1;   // wm: 64-row half; wn: 32-col quarter

    float acc[4][4][4] = {};

    // cp.async mapping: 256 threads, each loads rows (tid>>2) and (tid>>2)+64,
    // one 16B chunk (tid&3) per row, for both A and B.
    int ldRow   = tid >> 2;              // 0..63
    int ldChunk = (tid & 3) * 4;
    const float* aG = A  + (size_t)(bm + ldRow) * K + ldChunk;
    const float* bG = Wt + (size_t)(bn + ldRow) * K + ldChunk;
    unsigned base = (unsigned)__cvta_generic_to_shared(smg);
    unsigned aS = base + (unsigned)((ldRow * AST + ldChunk) * 4);
    unsigned bS = base + STG_BYTES + (unsigned)((ldRow * AST + ldChunk) * 4);

    // ldmatrix per-thread base addresses (stage 0) — verified mapping from R6.
    unsigned aF = base
        + (unsigned)(((wm*64 + (lane & 15)) * AST + ((lane >> 4) << 2)) * 4);
    unsigned bF = base + STG_BYTES
        + (unsigned)(((wn*32 + (lane & 7) + ((lane & 16) >> 1)) * AST + ((lane & 8) >> 1)) * 4);

    int nIt = K >> 4;

    // Prologue: stages 0 and 1
#pragma unroll
    for (int s = 0; s < 2; s++) {
#pragma unroll
        for (int i = 0; i < 2; i++) {
            CP_ASYNC16(aS + (unsigned)(s*2*STG_BYTES) + (unsigned)(i*64*AST*4),
                       aG + s*16 + (size_t)i*64*K);
            CP_ASYNC16(bS + (unsigned)(s*2*STG_BYTES) + (unsigned)(i*64*AST*4),
                       bG + s*16 + (size_t)i*64*K);
        }
        asm volatile("cp.async.commit_group;\n" ::);
    }

    for (int it = 0; it < nIt; it++) {
        asm volatile("cp.async.wait_group 1;\n" ::);   // stage it%3 resident
        __syncthreads();   // also: all warps done reading slot (it+2)%3 (iter it-1)

        if (it + 2 < nIt) {
            int s = (it + 2) % 3;
            const float* aGn = aG + (it + 2) * 16;
            const float* bGn = bG + (it + 2) * 16;
#pragma unroll
            for (int i = 0; i < 2; i++) {
                CP_ASYNC16(aS + (unsigned)(s*2*STG_BYTES) + (unsigned)(i*64*AST*4),
                           aGn + (size_t)i*64*K);
                CP_ASYNC16(bS + (unsigned)(s*2*STG_BYTES) + (unsigned)(i*64*AST*4),
                           bGn + (size_t)i*64*K);
            }
        }
        asm volatile("cp.async.commit_group;\n" ::);   // empty group ok at tail

        int cs = it % 3;
        unsigned aFs = aF + (unsigned)(cs * 2 * STG_BYTES);
        unsigned bFs = bF + (unsigned)(cs * 2 * STG_BYTES);
#pragma unroll
        for (int ks = 0; ks < 2; ks++) {
            unsigned a[4][4], b[2][4];
#pragma unroll
            for (int mt = 0; mt < 4; mt++)
                asm volatile(
                    "ldmatrix.sync.aligned.m8n8.x4.shared.b16 {%0,%1,%2,%3}, [%4];"
                    : "=r"(a[mt][0]), "=r"(a[mt][1]), "=r"(a[mt][2]), "=r"(a[mt][3])
                    : "r"(aFs + (unsigned)(mt * (16*AST*4) + ks * 32)));
#pragma unroll
            for (int np = 0; np < 2; np++)
                asm volatile(
                    "ldmatrix.sync.aligned.m8n8.x4.shared.b16 {%0,%1,%2,%3}, [%4];"
                    : "=r"(b[np][0]), "=r"(b[np][1]), "=r"(b[np][2]), "=r"(b[np][3])
                    : "r"(bFs + (unsigned)(np * (16*AST*4) + ks * 32)));
#pragma unroll
            for (int mt = 0; mt < 4; mt++)
#pragma unroll
                for (int np = 0; np < 2; np++) {
                    asm volatile(
                        "mma.sync.aligned.m16n8k8.row.col.f32.tf32.tf32.f32 "
                        "{%0,%1,%2,%3}, {%4,%5,%6,%7}, {%8,%9}, {%0,%1,%2,%3};"
                        : "+f"(acc[mt][2*np][0]), "+f"(acc[mt][2*np][1]),
                          "+f"(acc[mt][2*np][2]), "+f"(acc[mt][2*np][3])
                        : "r"(a[mt][0]), "r"(a[mt][1]), "r"(a[mt][2]), "r"(a[mt][3]),
                          "r"(b[np][0]), "r"(b[np][1]));
                    asm volatile(
                        "mma.sync.aligned.m16n8k8.row.col.f32.tf32.tf32.f32 "
                        "{%0,%1,%2,%3}, {%4,%5,%6,%7}, {%8,%9}, {%0,%1,%2,%3};"
                        : "+f"(acc[mt][2*np+1][0]), "+f"(acc[mt][2*np+1][1]),
                          "+f"(acc[mt][2*np+1][2]), "+f"(acc[mt][2*np+1][3])
                        : "r"(a[mt][0]), "r"(a[mt][1]), "r"(a[mt][2]), "r"(a[mt][3]),
                          "r"(b[np][2]), "r"(b[np][3]));
                }
        }
    }

    // Epilogue
    int g = lane >> 2, tg = lane & 3;
#pragma unroll
    for (int mt = 0; mt < 4; mt++) {
        int m0 = bm + wm*64 + mt*16 + g;
#pragma unroll
        for (int nt = 0; nt < 4; nt++) {
            int n0 = bn + wn*32 + nt*8 + tg*2;
            float bx = bias[n0], by = bias[n0 + 1];
#pragma unroll
            for (int hf = 0; hf < 2; hf++) {
                int m = m0 + hf*8;
                float rx = acc[mt][nt][hf*2 + 0] + bx;
                float ry = acc[mt][nt][hf*2 + 1] + by;
                if (RELU) { rx = fmaxf(rx, 0.f); ry = fmaxf(ry, 0.f); }
                size_t off = (size_t)m * N + n0;
                if (RES) {
                    float2 rr = *(const float2*)(res + off);
                    rx += rr.x; ry += rr.y;
                } else {
                    rx = roundtf(rx);
                    ry = roundtf(ry);
                }
                float2 o2; o2.x = rx; o2.y = ry;
                *(float2*)(C + off) = o2;
            }
        }
    }
}

// ---------------------------------------------------------------------------
// Fused flash attention with tf32 mma (mask is a no-op in the reference).
// Block: 256 threads = 8 warps. Tile: 128 q-rows x 64 kv per block.
// smem floats: Qs[128][68] | Ps[128][68] | Ks[64][68] | Vs[64][72]
// ---------------------------------------------------------------------------
#define QS_STRIDE 68
#define PS_STRIDE 68
#define KS_STRIDE 68
#define VS_STRIDE 72
#define SM_QS 0
#define SM_PS (128 * QS_STRIDE)
#define SM_KS (SM_PS + 128 * PS_STRIDE)
#define SM_VS (SM_KS + 64 * KS_STRIDE)
#define ATTN_SMEM_FLOATS (SM_VS + 64 * VS_STRIDE)
#define ATTN_SMEM_BYTES  (ATTN_SMEM_FLOATS * (int)sizeof(float))

__global__ __launch_bounds__(256) void attn_kernel(
    const float* __restrict__ q, const float* __restrict__ k,
    const float* __restrict__ v, float* __restrict__ ctx)
{
    extern __shared__ float sm[];
    float* Qs = sm + SM_QS;
    float* Ps = sm + SM_PS;
    float* Ks = sm + SM_KS;
    float* Vs = sm + SM_VS;

    int qt = blockIdx.x;
    int bh = blockIdx.y;
    int b = bh >> 4;
    int h = bh & 15;
    int tid  = threadIdx.x;
    int lane = tid & 31;
    int warp = tid >> 5;
    int g   = lane >> 2;
    int tig = lane & 3;

    size_t base_col = (size_t)h * DKK;
    int s0 = b * SS + qt * 128;
    int kbase = b * SS;

#pragma unroll
    for (int i = 0; i < 8; i++) {
        int f = i * 256 + tid;
        int r = f >> 4;
        int c = (f & 15) * 4;
        float4 t4 = *(const float4*)(q + (size_t)(s0 + r) * DD + base_col + c);
        Qs[r * QS_STRIDE + c + 0] = t4.x * 0.125f;
        Qs[r * QS_STRIDE + c + 1] = t4.y * 0.125f;
        Qs[r * QS_STRIDE + c + 2] = t4.z * 0.125f;
        Qs[r * QS_STRIDE + c + 3] = t4.w * 0.125f;
    }

    float O[8][4];
    float m0 = -1e30f, m1 = -1e30f, l0 = 0.f, l1 = 0.f;
#pragma unroll
    for (int nt = 0; nt < 8; nt++)
#pragma unroll
        for (int c = 0; c < 4; c++) O[nt][c] = 0.f;

    int qrow = warp * 16;

    for (int kv0 = 0; kv0 < SS; kv0 += 64) {
        __syncthreads();
#pragma unroll
        for (int i = 0; i < 4; i++) {
            int f = i * 256 + tid;
            int r = f >> 4;
            int c = (f & 15) * 4;
            float4 kt = *(const float4*)(k + (size_t)(kbase + kv0 + r) * DD + base_col + c);
            Ks[r * KS_STRIDE + c + 0] = kt.x;
            Ks[r * KS_STRIDE + c + 1] = kt.y;
            Ks[r * KS_STRIDE + c + 2] = kt.z;
            Ks[r * KS_STRIDE + c + 3] = kt.w;
            float4 vt = *(const float4*)(v + (size_t)(kbase + kv0 + r) * DD + base_col + c);
            Vs[r * VS_STRIDE + c + 0] = vt.x;
            Vs[r * VS_STRIDE + c + 1] = vt.y;
            Vs[r * VS_STRIDE + c + 2] = vt.z;
            Vs[r * VS_STRIDE + c + 3] = vt.w;
        }
        __syncthreads();

        float s[8][4];
#pragma unroll
        for (int nt = 0; nt < 8; nt++)
#pragma unroll
            for (int c = 0; c < 4; c++) s[nt][c] = 0.f;

#pragma unroll
        for (int ks = 0; ks < 8; ks++) {
            int kk = ks * 8;
            unsigned a0 = __float_as_uint(Qs[(qrow + g    ) * QS_STRIDE + kk + tig    ]);
            unsigned a1 = __float_as_uint(Qs[(qrow + g + 8) * QS_STRIDE + kk + tig    ]);
            unsigned a2 = __float_as_uint(Qs[(qrow + g    ) * QS_STRIDE + kk + tig + 4]);
            unsigned a3 = __float_as_uint(Qs[(qrow + g + 8) * QS_STRIDE + kk + tig + 4]);
#pragma unroll
            for (int nt = 0; nt < 8; nt++) {
                unsigned b0 = __float_as_uint(Ks[(nt * 8 + g) * KS_STRIDE + kk + tig    ]);
                unsigned b1 = __float_as_uint(Ks[(nt * 8 + g) * KS_STRIDE + kk + tig + 4]);
                asm volatile(
                    "mma.sync.aligned.m16n8k8.row.col.f32.tf32.tf32.f32 "
                    "{%0,%1,%2,%3}, {%4,%5,%6,%7}, {%8,%9}, {%0,%1,%2,%3};"
                    : "+f"(s[nt][0]), "+f"(s[nt][1]), "+f"(s[nt][2]), "+f"(s[nt][3])
                    : "r"(a0), "r"(a1), "r"(a2), "r"(a3), "r"(b0), "r"(b1));
            }
        }

        float rm0 = -1e30f, rm1 = -1e30f;
#pragma unroll
        for (int nt = 0; nt < 8; nt++) {
            rm0 = fmaxf(rm0, fmaxf(s[nt][0], s[nt][1]));
            rm1 = fmaxf(rm1, fmaxf(s[nt][2], s[nt][3]));
        }
#pragma unroll
        for (int o = 1; o < 4; o <<= 1) {
            rm0 = fmaxf(rm0, __shfl_xor_sync(0xffffffffu, rm0, o));
            rm1 = fmaxf(rm1, __shfl_xor_sync(0xffffffffu, rm1, o));
        }
        float mn0 = fmaxf(m0, rm0);
        float mn1 = fmaxf(m1, rm1);
        float corr0 = __expf(m0 - mn0);
        float corr1 = __expf(m1 - mn1);
        float ps0 = 0.f, ps1 = 0.f;
#pragma unroll
        for (int nt = 0; nt < 8; nt++) {
            s[nt][0] = __expf(s[nt][0] - mn0);
            s[nt][1] = __expf(s[nt][1] - mn0);
            s[nt][2] = __expf(s[nt][2] - mn1);
            s[nt][3] = __expf(s[nt][3] - mn1);
            ps0 += s[nt][0] + s[nt][1];
            ps1 += s[nt][2] + s[nt][3];
            float2 p01; p01.x = s[nt][0]; p01.y = s[nt][1];
            float2 p23; p23.x = s[nt][2]; p23.y = s[nt][3];
            *(float2*)&Ps[(qrow + g    ) * PS_STRIDE + nt * 8 + tig * 2] = p01;
            *(float2*)&Ps[(qrow + g + 8) * PS_STRIDE + nt * 8 + tig * 2] = p23;
        }
#pragma unroll
        for (int o = 1; o < 4; o <<= 1) {
            ps0 += __shfl_xor_sync(0xffffffffu, ps0, o);
            ps1 += __shfl_xor_sync(0xffffffffu, ps1, o);
        }
        l0 = l0 * corr0 + ps0;
        l1 = l1 * corr1 + ps1;
        m0 = mn0; m1 = mn1;
#pragma unroll
        for (int nt = 0; nt < 8; nt++) {
            O[nt][0] *= corr0; O[nt][1] *= corr0;
            O[nt][2] *= corr1; O[nt][3] *= corr1;
        }
        __syncthreads();

#pragma unroll
        for (int ks = 0; ks < 8; ks++) {
            int kk = ks * 8;
            unsigned a0 = __float_as_uint(Ps[(qrow + g    ) * PS_STRIDE + kk + tig    ]);
            unsigned a1 = __float_as_uint(Ps[(qrow + g + 8) * PS_STRIDE + kk + tig    ]);
            unsigned a2 = __float_as_uint(Ps[(qrow + g    ) * PS_STRIDE + kk + tig + 4]);
            unsigned a3 = __float_as_uint(Ps[(qrow + g + 8) * PS_STRIDE + kk + tig + 4]);
#pragma unroll
            for (int nt = 0; nt < 8; nt++) {
                unsigned b0 = __float_as_uint(Vs[(kk + tig    ) * VS_STRIDE + nt * 8 + g]);
                unsigned b1 = __float_as_uint(Vs[(kk + tig + 4) * VS_STRIDE + nt * 8 + g]);
                asm volatile(
                    "mma.sync.aligned.m16n8k8.row.col.f32.tf32.tf32.f32 "
                    "{%0,%1,%2,%3}, {%4,%5,%6,%7}, {%8,%9}, {%0,%1,%2,%3};"
                    : "+f"(O[nt][0]), "+f"(O[nt][1]), "+f"(O[nt][2]), "+f"(O[nt][3])
                    : "r"(a0), "r"(a1), "r"(a2), "r"(a3), "r"(b0), "r"(b1));
            }
        }
    }

    float inv0 = 1.f / l0;
    float inv1 = 1.f / l1;
    int r0 = s0 + warp * 16 + g;
#pragma unroll
    for (int nt = 0; nt < 8; nt++) {
        int c0 = nt * 8 + tig * 2;
        float2 o01; o01.x = roundtf(O[nt][0] * inv0); o01.y = roundtf(O[nt][1] * inv0);
        float2 o23; o23.x = roundtf(O[nt][2] * inv1); o23.y = roundtf(O[nt][3] * inv1);
        *(float2*)(ctx + (size_t)(r0    ) * DD + base_col + c0) = o01;
        *(float2*)(ctx + (size_t)(r0 + 8) * DD + base_col + c0) = o23;
    }
}

// ---------------------------------------------------------------------------
// Launch. Order puts the V-projection GEMM at launch index 5 (ncu -s 5 -c 1).
// ---------------------------------------------------------------------------
extern "C" void kernel_launch(void* const* d_in, const int* in_sizes, int n_in,
                              void* d_out, int out_size)
{
    const float* x  = (const float*)d_in[0];
    // d_in[1] = src_mask (provably no effect in the reference; ignored)
    const float* Wq = (const float*)d_in[2];
    const float* bq = (const float*)d_in[3];
    const float* Wk = (const float*)d_in[4];
    const float* bk = (const float*)d_in[5];
    const float* Wv = (const float*)d_in[6];
    const float* bv = (const float*)d_in[7];
    const float* Wo = (const float*)d_in[8];
    const float* bo = (const float*)d_in[9];
    const float* W1 = (const float*)d_in[10];
    const float* b1 = (const float*)d_in[11];
    const float* W2 = (const float*)d_in[12];
    const float* b2 = (const float*)d_in[13];
    const float* a1 = (const float*)d_in[14];
    const float* g1 = (const float*)d_in[15];
    const float* a2 = (const float*)d_in[16];
    const float* g2 = (const float*)d_in[17];
    float* out = (float*)d_out;

    float *h, *q, *k, *v, *ctx, *x2, *h2, *ff;
    float *wtq, *wtk, *wtv, *wto, *wt1, *wt2;
    cudaGetSymbolAddress((void**)&h,   g_h);
    cudaGetSymbolAddress((void**)&q,   g_q);
    cudaGetSymbolAddress((void**)&k,   g_k);
    cudaGetSymbolAddress((void**)&v,   g_v);
    cudaGetSymbolAddress((void**)&ctx, g_ctx);
    cudaGetSymbolAddress((void**)&x2,  g_x2);
    cudaGetSymbolAddress((void**)&h2,  g_h2);
    cudaGetSymbolAddress((void**)&ff,  g_ff);
    cudaGetSymbolAddress((void**)&wtq, g_wtq);
    cudaGetSymbolAddress((void**)&wtk, g_wtk);
    cudaGetSymbolAddress((void**)&wtv, g_wtv);
    cudaGetSymbolAddress((void**)&wto, g_wto);
    cudaGetSymbolAddress((void**)&wt1, g_wt1);
    cudaGetSymbolAddress((void**)&wt2, g_wt2);

    cudaFuncSetAttribute(attn_kernel,
                         cudaFuncAttributeMaxDynamicSharedMemorySize,
                         ATTN_SMEM_BYTES);
    cudaFuncSetAttribute(tf32_gemm<false, false>,
                         cudaFuncAttributeMaxDynamicSharedMemorySize, GEMM_SMEM);
    cudaFuncSetAttribute(tf32_gemm<false, true>,
                         cudaFuncAttributeMaxDynamicSharedMemorySize, GEMM_SMEM);
    cudaFuncSetAttribute(tf32_gemm<true, false>,
                         cudaFuncAttributeMaxDynamicSharedMemorySize, GEMM_SMEM);

    dim3 gD(DD / 128, MROWS / 128);      // (8, 32)
    dim3 gF(DFFN / 128, MROWS / 128);    // (32, 32)

    // 0: four DxD weight transposes (batched)
    transpose_round4<<<4096, 256>>>(Wq, Wk, Wv, Wo, wtq, wtk, wtv, wto);
    // 1: FFN weight transposes (batched)
    transpose_round_ffn<<<8192, 256>>>(W1, W2, wt1, wt2);
    // 2: ln1
    ln_kernel<<<MROWS, 256>>>(x, h, a1, g1);
    // 3,4,5: Q, K, V projections  (launch 5 = V gemm -> profiled by ncu)
    tf32_gemm<false, false><<<gD, 256, GEMM_SMEM>>>(h, wtq, bq, nullptr, q, MROWS, DD, DD);
    tf32_gemm<false, false><<<gD, 256, GEMM_SMEM>>>(h, wtk, bk, nullptr, k, MROWS, DD, DD);
    tf32_gemm<false, false><<<gD, 256, GEMM_SMEM>>>(h, wtv, bv, nullptr, v, MROWS, DD, DD);
    // 6: attention
    attn_kernel<<<dim3(SS / 128, BB * HH), 256, ATTN_SMEM_BYTES>>>(q, k, v, ctx);
    // 7: out-proj + residual
    tf32_gemm<false, true><<<gD, 256, GEMM_SMEM>>>(ctx, wto, bo, x, x2, MROWS, DD, DD);
    // 8: ln2
    ln_kernel<<<MROWS, 256>>>(x2, h2, a2, g2);
    // 9: ffn1 with relu
    tf32_gemm<true, false><<<gF, 256, GEMM_SMEM>>>(h2, wt1, b1, nullptr, ff, MROWS, DFFN, DD);
    // 10: ffn2 + residual -> output
    tf32_gemm<false, true><<<gD, 256, GEMM_SMEM>>>(ff, wt2, b2, x2, out, MROWS, DD, DFFN);
}